// round 16
// baseline (speedup 1.0000x reference)
#include <cuda_runtime.h>
#include <cstdint>
#define NN 20000
#define EE 320000
using u64 = unsigned long long;

__device__ float g_x[NN*3];
__device__ float g_h[NN*64];
__device__ float g_A[NN*64];
__device__ float g_B[NN*64];
__device__ float g_agg[NN*64];
__device__ float g_xacc[NN*3];
__device__ float g_cnt[NN];
__device__ float g_invc[NN];

__device__ __forceinline__ float silu(float v){ return __fdividef(v,1.f+__expf(-v)); }
__device__ __forceinline__ u64 mk2(float a,float b){u64 r;asm("mov.b64 %0,{%1,%2};":"=l"(r):"f"(a),"f"(b));return r;}
__device__ __forceinline__ u64 pack2(float x){u64 r;asm("mov.b64 %0,{%1,%1};":"=l"(r):"f"(x));return r;}
__device__ __forceinline__ u64 ffma2(u64 a,u64 b,u64 c){u64 d;asm("fma.rn.f32x2 %0,%1,%2,%3;":"=l"(d):"l"(a),"l"(b),"l"(c));return d;}
__device__ __forceinline__ u64 add2(u64 a,u64 b){u64 d;asm("add.rn.f32x2 %0,%1,%2;":"=l"(d):"l"(a),"l"(b));return d;}
__device__ __forceinline__ u64 mul2(u64 a,u64 b){u64 d;asm("mul.rn.f32x2 %0,%1,%2;":"=l"(d):"l"(a),"l"(b));return d;}
__device__ __forceinline__ float2 unpk(u64 a){float x,y;asm("mov.b64 {%0,%1},%2;":"=f"(x),"=f"(y):"l"(a));return make_float2(x,y);}
__device__ __forceinline__ float fin(u64 a){float2 v=unpk(a);return v.x+v.y;}
// packed silu on a register pair: v/(1+exp(-v)) elementwise
__device__ __forceinline__ u64 silu2(u64 v){
  u64 t=mul2(v,pack2(-1.4426950408889634f));
  float2 tp=unpk(t);
  float e0,e1;
  asm("ex2.approx.f32 %0,%1;":"=f"(e0):"f"(tp.x));
  asm("ex2.approx.f32 %0,%1;":"=f"(e1):"f"(tp.y));
  u64 d=add2(mk2(e0,e1),pack2(1.f));
  float2 dp=unpk(d);
  float r0,r1;
  asm("rcp.approx.f32 %0,%1;":"=f"(r0):"f"(dp.x));
  asm("rcp.approx.f32 %0,%1;":"=f"(r1):"f"(dp.y));
  return mul2(v,mk2(r0,r1));
}

// ======== dual-width edge matvec, register-lean row-chunked (validated R13) ========
template<int K>
__device__ __forceinline__ void mv8d(const float* vb,const float* W,int q,u64* accA,u64* accB){
#pragma unroll 2
  for(int k4=0;k4<K;k4+=4){
    ulonglong2 w0=*(const ulonglong2*)(W+(k4+0)*64+q*4);
    ulonglong2 w1=*(const ulonglong2*)(W+(k4+1)*64+q*4);
    ulonglong2 w2=*(const ulonglong2*)(W+(k4+2)*64+q*4);
    ulonglong2 w3=*(const ulonglong2*)(W+(k4+3)*64+q*4);
#pragma unroll
    for(int h=0;h<2;h++){
      u64* acc = h? accB : accA;
      const float* vp=vb+(h*4)*136+k4;
      float4 a0=*(const float4*)(vp);
      float4 a1=*(const float4*)(vp+136);
      float4 a2=*(const float4*)(vp+272);
      float4 a3=*(const float4*)(vp+408);
#define RJ(w,f0,f1,f2,f3) { \
      u64 p0=pack2(f0),p1=pack2(f1),p2=pack2(f2),p3=pack2(f3); \
      acc[0]=ffma2(w.x,p0,acc[0]); acc[1]=ffma2(w.y,p0,acc[1]); \
      acc[2]=ffma2(w.x,p1,acc[2]); acc[3]=ffma2(w.y,p1,acc[3]); \
      acc[4]=ffma2(w.x,p2,acc[4]); acc[5]=ffma2(w.y,p2,acc[5]); \
      acc[6]=ffma2(w.x,p3,acc[6]); acc[7]=ffma2(w.y,p3,acc[7]); }
      RJ(w0,a0.x,a1.x,a2.x,a3.x)
      RJ(w1,a0.y,a1.y,a2.y,a3.y)
      RJ(w2,a0.z,a1.z,a2.z,a3.z)
      RJ(w3,a0.w,a1.w,a2.w,a3.w)
#undef RJ
    }
  }
}
__device__ __forceinline__ void acc_init8(u64* acc,const float* sb,int q){
  u64 b01=((const u64*)sb)[q*2], b23=((const u64*)sb)[q*2+1];
#pragma unroll
  for(int r=0;r<4;r++){ acc[2*r]=b01; acc[2*r+1]=b23; }
}

// ======== node-side scalar machinery (validated) ========
__device__ __forceinline__ void stageW(u64* dst,const float* __restrict__ src,int K,int tid,int nthr){
  int tot=(K/2)*64;
  for(int i=tid;i<tot;i+=nthr){
    int kp=i>>6,c=i&63;
    u64 v=mk2(src[(2*kp)*64+c],src[(2*kp+1)*64+c]);
    dst[(kp<<6)+((c&2)?32:0)+((c>>2)<<1)+(c&1)]=v;
  }
}
__device__ __forceinline__ void ainit(u64* acc,const float* b4,int q){
  float4 b=*(const float4*)&b4[q*4];
#pragma unroll
  for(int r=0;r<4;r++){
    acc[4*r]=mk2(b.x,0.f); acc[4*r+1]=mk2(b.y,0.f);
    acc[4*r+2]=mk2(b.z,0.f); acc[4*r+3]=mk2(b.w,0.f);
  }
}
__device__ __forceinline__ void a0init(u64* acc){
#pragma unroll
  for(int i=0;i<16;i++) acc[i]=0ull;
}
template<int K>
__device__ __forceinline__ void mv8p(const float* vb,int ST,const u64* Wp,int q,u64* acc){
#pragma unroll 8
  for(int kp=0;kp<K/2;kp+=2){
    ulonglong2 a0=*(const ulonglong2*)(vb+2*kp);
    ulonglong2 a1=*(const ulonglong2*)(vb+ST+2*kp);
    ulonglong2 a2=*(const ulonglong2*)(vb+2*ST+2*kp);
    ulonglong2 a3=*(const ulonglong2*)(vb+3*ST+2*kp);
    const u64* wr=Wp+(kp<<6)+2*q;
    ulonglong2 wa0=*(const ulonglong2*)wr;
    ulonglong2 wb0=*(const ulonglong2*)(wr+32);
    ulonglong2 wa1=*(const ulonglong2*)(wr+64);
    ulonglong2 wb1=*(const ulonglong2*)(wr+96);
#define RSTEP(r,A) \
    acc[4*r+0]=ffma2(A.x,wa0.x,acc[4*r+0]); acc[4*r+1]=ffma2(A.x,wa0.y,acc[4*r+1]); \
    acc[4*r+2]=ffma2(A.x,wb0.x,acc[4*r+2]); acc[4*r+3]=ffma2(A.x,wb0.y,acc[4*r+3]); \
    acc[4*r+0]=ffma2(A.y,wa1.x,acc[4*r+0]); acc[4*r+1]=ffma2(A.y,wa1.y,acc[4*r+1]); \
    acc[4*r+2]=ffma2(A.y,wb1.x,acc[4*r+2]); acc[4*r+3]=ffma2(A.y,wb1.y,acc[4*r+3]);
    RSTEP(0,a0) RSTEP(1,a1) RSTEP(2,a2) RSTEP(3,a3)
#undef RSTEP
  }
}

__global__ void k_zero(){
  int i=blockIdx.x*blockDim.x+threadIdx.x;
  if(i<NN) g_cnt[i]=0.f;
  if(i<NN*3) g_xacc[i]=0.f;
}
__global__ void k_count(const int* __restrict__ erow){
  int e=blockIdx.x*blockDim.x+threadIdx.x;
  if(e<EE) atomicAdd(&g_cnt[erow[e]],1.f);
}

// h0=h16@Wi+bi ; A=h0@EA+eb ; B=h0@EB ; init x, invc, agg=0  (validated)
__global__ void __launch_bounds__(256) k_embed(
    const float* __restrict__ h16,const float* __restrict__ xin,
    const float* __restrict__ Wi,const float* __restrict__ bi,
    const float* __restrict__ EA,const float* __restrict__ eb,
    const float* __restrict__ EB){
  extern __shared__ char sr[];
  u64* sWip=(u64*)sr; u64* sEAp=(u64*)(sr+4096); u64* sEBp=(u64*)(sr+20480);
  float* sbi=(float*)(sr+36864); float* seb=(float*)(sr+37120);
  float* vbase=(float*)(sr+37376);
  const int tid=threadIdx.x,wid=tid>>5,lane=tid&31,q=lane&15,g2=lane>>4;
  stageW(sWip,Wi,16,tid,256);
  stageW(sEAp,EA,64,tid,256);
  stageW(sEBp,EB,64,tid,256);
  if(tid<64){sbi[tid]=bi[tid];seb[tid]=eb[tid];}
  float* vb=vbase+wid*(8*84);
  int nbase=blockIdx.x*64+wid*8;
#pragma unroll
  for(int t=0;t<4;t++){
    int e=t*2+g2,n=nbase+e;
    if(q<4){
      float4 v=make_float4(0,0,0,0);
      if(n<NN) v=*(const float4*)&h16[n*16+q*4];
      *(float4*)&vb[e*84+q*4]=v;
    }
    if(n<NN) *(float4*)&g_agg[n*64+q*4]=make_float4(0,0,0,0);
  }
  if(lane<8){int n=nbase+lane; if(n<NN) g_invc[n]=__fdividef(1.f,fmaxf(g_cnt[n],1.f));}
  if(lane<24){int e=lane/3,d=lane-3*(lane/3),n=nbase+e; if(n<NN) g_x[n*3+d]=xin[n*3+d];}
  __syncthreads();
  u64 acc[16];
  ainit(acc,sbi,q);
  mv8p<16>(vb+g2*4*84,84,sWip,q,acc);
  __syncwarp();
#pragma unroll
  for(int r=0;r<4;r++){
    int e=g2*4+r,n=nbase+e;
    float4 h0=make_float4(fin(acc[4*r]),fin(acc[4*r+1]),fin(acc[4*r+2]),fin(acc[4*r+3]));
    *(float4*)&vb[e*84+16+q*4]=h0;
    if(n<NN) *(float4*)&g_h[n*64+q*4]=h0;
  }
  __syncwarp();
  ainit(acc,seb,q);
  mv8p<64>(vb+g2*4*84+16,84,sEAp,q,acc);
#pragma unroll
  for(int r=0;r<4;r++){
    int n=nbase+g2*4+r;
    if(n<NN) *(float4*)&g_A[n*64+q*4]=make_float4(fin(acc[4*r]),fin(acc[4*r+1]),fin(acc[4*r+2]),fin(acc[4*r+3]));
  }
  a0init(acc);
  mv8p<64>(vb+g2*4*84+16,84,sEBp,q,acc);
#pragma unroll
  for(int r=0;r<4;r++){
    int n=nbase+g2*4+r;
    if(n<NN) *(float4*)&g_B[n*64+q*4]=make_float4(fin(acc[4*r]),fin(acc[4*r+1]),fin(acc[4*r+2]),fin(acc[4*r+3]));
  }
}

// ======== edge kernel: 16 edges/warp, 128 edges/block, 3 CTAs/SM, packed f32x2 epilogues ========
__global__ void __launch_bounds__(256,3) k_edge(
    const int* __restrict__ erow,const int* __restrict__ ecol,
    const float* __restrict__ w1c,const float* __restrict__ W2,
    const float* __restrict__ b2,const float* __restrict__ CW1,
    const float* __restrict__ cb1,const float* __restrict__ cw2){
  extern __shared__ char sr[];
  float* sW2=(float*)sr; float* sC1=(float*)(sr+16384);
  float* sw1c=(float*)(sr+32768); float* sb2=(float*)(sr+33024);
  float* scb1=(float*)(sr+33280); float* scw2=(float*)(sr+33536);
  float* wsmb=(float*)(sr+33792);
  const int tid=threadIdx.x,wid=tid>>5,lane=tid&31,q=lane&15,g2=lane>>4;
  for(int i=tid;i<1024;i+=256){((float4*)sW2)[i]=((const float4*)W2)[i];((float4*)sC1)[i]=((const float4*)CW1)[i];}
  if(tid<64){sw1c[tid]=w1c[tid];sb2[tid]=b2[tid];scb1[tid]=cb1[tid];scw2[tid]=cw2[tid];}
  float* wsm=wsmb+wid*1216;
  float* m1b=wsm;                 // 1088 floats, reused as mb after matvec1
  float* dfb=wsm+1088; float* rdb=wsm+1136; float* icb=wsm+1152;
  int* rwb=(int*)(wsm+1168); int* clb=(int*)(wsm+1184);
  int ebase=blockIdx.x*128+wid*16;
  if(lane<16){
    int e=ebase+lane,r=erow[e],c=ecol[e];
    rwb[lane]=r; clb[lane]=c;
    float dx=g_x[r*3]-g_x[c*3],dy=g_x[r*3+1]-g_x[c*3+1],dz=g_x[r*3+2]-g_x[c*3+2];
    dfb[lane*3]=dx; dfb[lane*3+1]=dy; dfb[lane*3+2]=dz;
    rdb[lane]=dx*dx+dy*dy+dz*dz; icb[lane]=g_invc[r];
  }
  __syncthreads();
  { // phase1: m1 = silu(A[r]+B[c]+rad*w1c), 16 edges, packed
    ulonglong2 wc2=*(const ulonglong2*)&sw1c[q*4];
#pragma unroll
    for(int t=0;t<8;t++){
      int e=t*2+g2;
      ulonglong2 a2v=*(const ulonglong2*)&g_A[rwb[e]*64+q*4];
      ulonglong2 b2v=*(const ulonglong2*)&g_B[clb[e]*64+q*4];
      u64 r2=pack2(rdb[e]);
      u64 v01=ffma2(r2,wc2.x,add2(a2v.x,b2v.x));
      u64 v23=ffma2(r2,wc2.y,add2(a2v.y,b2v.y));
      *(ulonglong2*)&m1b[e*68+q*4]=make_ulonglong2(silu2(v01),silu2(v23));
    }
  }
  __syncwarp();
  u64 accA[8],accB[8];
  acc_init8(accA,sb2,q); acc_init8(accB,sb2,q);
  mv8d<64>(m1b+g2*68,sW2,q,accA,accB);
  __syncwarp();          // all lanes done reading m1b before overwrite
  // epilogue1: m = silu(.), red into agg, restage; straight-line A then B
#pragma unroll
  for(int r=0;r<4;r++){
    int e=2*r+g2;
    u64 m01=silu2(accA[2*r]), m23=silu2(accA[2*r+1]);
    *(ulonglong2*)&m1b[e*68+q*4]=make_ulonglong2(m01,m23);
    float2 f01=unpk(m01), f23=unpk(m23);
    asm volatile("red.global.add.v4.f32 [%0],{%1,%2,%3,%4};"
                 ::"l"(&g_agg[rwb[e]*64+q*4]),"f"(f01.x),"f"(f01.y),"f"(f23.x),"f"(f23.y):"memory");
  }
#pragma unroll
  for(int r=0;r<4;r++){
    int e=2*(r+4)+g2;
    u64 m01=silu2(accB[2*r]), m23=silu2(accB[2*r+1]);
    *(ulonglong2*)&m1b[e*68+q*4]=make_ulonglong2(m01,m23);
    float2 f01=unpk(m01), f23=unpk(m23);
    asm volatile("red.global.add.v4.f32 [%0],{%1,%2,%3,%4};"
                 ::"l"(&g_agg[rwb[e]*64+q*4]),"f"(f01.x),"f"(f01.y),"f"(f23.x),"f"(f23.y):"memory");
  }
  __syncwarp();
  acc_init8(accA,scb1,q); acc_init8(accB,scb1,q);
  mv8d<64>(m1b+g2*68,sC1,q,accA,accB);
  // epilogue2: phi partials, packed dot with cw2
  ulonglong2 c2=*(const ulonglong2*)&scw2[q*4];
  float s[8];
#pragma unroll
  for(int r=0;r<4;r++)
    s[r]=fin(ffma2(silu2(accA[2*r+1]),c2.y,mul2(silu2(accA[2*r]),c2.x)));
#pragma unroll
  for(int r=0;r<4;r++)
    s[r+4]=fin(ffma2(silu2(accB[2*r+1]),c2.y,mul2(silu2(accB[2*r]),c2.x)));
#pragma unroll
  for(int off=1;off<16;off<<=1){
#pragma unroll
    for(int r=0;r<8;r++) s[r]+=__shfl_xor_sync(0xffffffffu,s[r],off);
  }
  if(q<12){
    int j=q/3,d=q-3*j;
    int e0=2*j+g2, e1=2*(j+4)+g2;
    atomicAdd(&g_xacc[rwb[e0]*3+d], dfb[e0*3+d]*s[j]*icb[e0]);
    atomicAdd(&g_xacc[rwb[e1]*3+d], dfb[e1*3+d]*s[j+4]*icb[e1]);
  }
}

// ======== node kernel: single 32KB weight buffer, re-staged per phase, 3 CTAs/SM (validated R15) ========
__global__ void __launch_bounds__(256,3) k_node(
    const float* __restrict__ NW1,const float* __restrict__ nb1,
    const float* __restrict__ NW2,const float* __restrict__ nb2,
    const float* __restrict__ WA,const float* __restrict__ ba,
    const float* __restrict__ WB,int last,float* __restrict__ outp){
  extern __shared__ char sr[];
  u64* W0=(u64*)sr;
  float* snb1=(float*)(sr+32768); float* snb2=(float*)(sr+33024);
  float* sba=(float*)(sr+33280);
  float* vbase=(float*)(sr+33536);
  const int tid=threadIdx.x,wid=tid>>5,lane=tid&31,q=lane&15,g2=lane>>4;
  stageW(W0,NW1,128,tid,256);
  if(tid<64){snb1[tid]=nb1[tid];snb2[tid]=nb2[tid];sba[tid]=ba[tid];}
  float* vb=vbase+wid*1056;
  int nbase=blockIdx.x*64+wid*8;
#pragma unroll
  for(int t=0;t<4;t++){
    int e=t*2+g2,n=nbase+e;
    float4 h4=make_float4(0,0,0,0),a4=make_float4(0,0,0,0);
    if(n<NN){
      h4=*(const float4*)&g_h[n*64+q*4];
      a4=*(const float4*)&g_agg[n*64+q*4];
      *(float4*)&g_agg[n*64+q*4]=make_float4(0,0,0,0);
    }
    *(float4*)&vb[e*132+q*4]=h4;
    *(float4*)&vb[e*132+64+q*4]=a4;
  }
  if(lane<24){
    int e=lane/3,d=lane-3*(lane/3),n=nbase+e;
    if(n<NN){
      float nx=g_x[n*3+d]+g_xacc[n*3+d];
      g_x[n*3+d]=nx; g_xacc[n*3+d]=0.f;
      if(last) outp[NN*64+n*3+d]=nx;
    }
  }
  __syncthreads();
  u64 acc[16];
  ainit(acc,snb1,q);
  mv8p<128>(vb+g2*4*132,132,W0,q,acc);
  __syncwarp();
#pragma unroll
  for(int r=0;r<4;r++){
    int e=g2*4+r;
    *(float4*)&vb[e*132+64+q*4]=make_float4(
      silu(fin(acc[4*r])),silu(fin(acc[4*r+1])),silu(fin(acc[4*r+2])),silu(fin(acc[4*r+3])));
  }
  __syncthreads();
  stageW(W0,NW2,64,tid,256);      // NW1 dead
  __syncthreads();
  ainit(acc,snb2,q);
  mv8p<64>(vb+g2*4*132+64,132,W0,q,acc);
  __syncwarp();
#pragma unroll
  for(int r=0;r<4;r++){
    int e=g2*4+r,n=nbase+e;
    float4 ho=*(const float4*)&vb[e*132+q*4];
    float4 hn=make_float4(ho.x+fin(acc[4*r]),ho.y+fin(acc[4*r+1]),
                          ho.z+fin(acc[4*r+2]),ho.w+fin(acc[4*r+3]));
    *(float4*)&vb[e*132+q*4]=hn;
    if(n<NN) *(float4*)&g_h[n*64+q*4]=hn;
  }
  __syncthreads();
  stageW(W0,WA,64,tid,256);       // NW2 dead
  if(!last) stageW(W0+2048,WB,64,tid,256);
  __syncthreads();
  ainit(acc,sba,q);
  mv8p<64>(vb+g2*4*132,132,W0,q,acc);
  if(last){
#pragma unroll
    for(int r=0;r<4;r++){
      int n=nbase+g2*4+r;
      if(n<NN) *(float4*)&outp[n*64+q*4]=make_float4(fin(acc[4*r]),fin(acc[4*r+1]),fin(acc[4*r+2]),fin(acc[4*r+3]));
    }
  } else {
#pragma unroll
    for(int r=0;r<4;r++){
      int n=nbase+g2*4+r;
      if(n<NN) *(float4*)&g_A[n*64+q*4]=make_float4(fin(acc[4*r]),fin(acc[4*r+1]),fin(acc[4*r+2]),fin(acc[4*r+3]));
    }
    a0init(acc);
    mv8p<64>(vb+g2*4*132,132,W0+2048,q,acc);
#pragma unroll
    for(int r=0;r<4;r++){
      int n=nbase+g2*4+r;
      if(n<NN) *(float4*)&g_B[n*64+q*4]=make_float4(fin(acc[4*r]),fin(acc[4*r+1]),fin(acc[4*r+2]),fin(acc[4*r+3]));
    }
  }
}

extern "C" void kernel_launch(void* const* d_in,const int* in_sizes,int n_in,
                              void* d_out,int out_size){
  const float* h16=(const float*)d_in[0];
  const float* xin=(const float*)d_in[1];
  const int*   ei =(const int*  )d_in[2];
  const float* Wi =(const float*)d_in[3];
  const float* bi =(const float*)d_in[4];
  const float* ew1=(const float*)d_in[5];
  const float* eb1=(const float*)d_in[6];
  const float* ew2=(const float*)d_in[7];
  const float* eb2=(const float*)d_in[8];
  const float* cw1=(const float*)d_in[9];
  const float* cb1=(const float*)d_in[10];
  const float* cw2=(const float*)d_in[11];
  const float* nw1=(const float*)d_in[12];
  const float* nb1=(const float*)d_in[13];
  const float* nw2=(const float*)d_in[14];
  const float* nb2=(const float*)d_in[15];
  const float* Wo =(const float*)d_in[16];
  const float* bo =(const float*)d_in[17];
  float* outp=(float*)d_out;
  const int* erow=ei; const int* ecol=ei+EE;

  const int SME=58880, SMEDGE=(8448+8*1216)*4, SMN=67328;
  cudaFuncSetAttribute(k_embed,cudaFuncAttributeMaxDynamicSharedMemorySize,SME);
  cudaFuncSetAttribute(k_edge, cudaFuncAttributeMaxDynamicSharedMemorySize,SMEDGE);
  cudaFuncSetAttribute(k_node, cudaFuncAttributeMaxDynamicSharedMemorySize,SMN);

  const int NB=(NN+63)/64;
  k_zero<<<(NN*3+255)/256,256>>>();
  k_count<<<(EE+255)/256,256>>>(erow);
  k_embed<<<NB,256,SME>>>(h16,xin,Wi,bi,ew1,eb1,ew1+64*64);
  for(int l=0;l<4;l++){
    k_edge<<<EE/128,256,SMEDGE>>>(erow,ecol,ew1+l*129*64+128*64,ew2+l*4096,eb2+l*64,
                                  cw1+l*4096,cb1+l*64,cw2+l*64);
    int last=(l==3);
    const float* WA = last ? Wo : ew1+(l+1)*129*64;
    const float* ba = last ? bo : eb1+(l+1)*64;
    const float* WB = last ? Wo : WA+64*64;
    k_node<<<NB,256,SMN>>>(nw1+l*128*64,nb1+l*64,nw2+l*4096,nb2+l*64,WA,ba,WB,last,outp);
  }
}

// round 17
// speedup vs baseline: 1.0552x; 1.0552x over previous
#include <cuda_runtime.h>
#include <cstdint>
#define NN 20000
#define EE 320000
using u64 = unsigned long long;

__device__ float g_x[NN*3];
__device__ float g_h[NN*64];
__device__ float g_A[NN*64];
__device__ float g_B[NN*64];
__device__ float g_agg[NN*64];
__device__ float g_xacc[NN*3];
__device__ float g_cnt[NN];
__device__ float g_invc[NN];

__device__ __forceinline__ float silu(float v){ return __fdividef(v,1.f+__expf(-v)); }
__device__ __forceinline__ u64 mk2(float a,float b){u64 r;asm("mov.b64 %0,{%1,%2};":"=l"(r):"f"(a),"f"(b));return r;}
__device__ __forceinline__ u64 pack2(float x){u64 r;asm("mov.b64 %0,{%1,%1};":"=l"(r):"f"(x));return r;}
__device__ __forceinline__ u64 ffma2(u64 a,u64 b,u64 c){u64 d;asm("fma.rn.f32x2 %0,%1,%2,%3;":"=l"(d):"l"(a),"l"(b),"l"(c));return d;}
__device__ __forceinline__ float2 unpk(u64 a){float x,y;asm("mov.b64 {%0,%1},%2;":"=f"(x),"=f"(y):"l"(a));return make_float2(x,y);}
__device__ __forceinline__ float fin(u64 a){float2 v=unpk(a);return v.x+v.y;}

// ======== dual-width edge matvec, register-lean row-chunked (validated R13/R15) ========
template<int K>
__device__ __forceinline__ void mv8d(const float* vb,const float* W,int q,u64* accA,u64* accB){
#pragma unroll 4
  for(int k4=0;k4<K;k4+=4){
    ulonglong2 w0=*(const ulonglong2*)(W+(k4+0)*64+q*4);
    ulonglong2 w1=*(const ulonglong2*)(W+(k4+1)*64+q*4);
    ulonglong2 w2=*(const ulonglong2*)(W+(k4+2)*64+q*4);
    ulonglong2 w3=*(const ulonglong2*)(W+(k4+3)*64+q*4);
#pragma unroll
    for(int h=0;h<2;h++){
      u64* acc = h? accB : accA;
      const float* vp=vb+(h*4)*136+k4;
      float4 a0=*(const float4*)(vp);
      float4 a1=*(const float4*)(vp+136);
      float4 a2=*(const float4*)(vp+272);
      float4 a3=*(const float4*)(vp+408);
#define RJ(w,f0,f1,f2,f3) { \
      u64 p0=pack2(f0),p1=pack2(f1),p2=pack2(f2),p3=pack2(f3); \
      acc[0]=ffma2(w.x,p0,acc[0]); acc[1]=ffma2(w.y,p0,acc[1]); \
      acc[2]=ffma2(w.x,p1,acc[2]); acc[3]=ffma2(w.y,p1,acc[3]); \
      acc[4]=ffma2(w.x,p2,acc[4]); acc[5]=ffma2(w.y,p2,acc[5]); \
      acc[6]=ffma2(w.x,p3,acc[6]); acc[7]=ffma2(w.y,p3,acc[7]); }
      RJ(w0,a0.x,a1.x,a2.x,a3.x)
      RJ(w1,a0.y,a1.y,a2.y,a3.y)
      RJ(w2,a0.z,a1.z,a2.z,a3.z)
      RJ(w3,a0.w,a1.w,a2.w,a3.w)
#undef RJ
    }
  }
}
__device__ __forceinline__ void acc_init8(u64* acc,const float* sb,int q){
  u64 b01=((const u64*)sb)[q*2], b23=((const u64*)sb)[q*2+1];
#pragma unroll
  for(int r=0;r<4;r++){ acc[2*r]=b01; acc[2*r+1]=b23; }
}

// ======== node-side scalar machinery (validated) ========
__device__ __forceinline__ void stageW(u64* dst,const float* __restrict__ src,int K,int tid,int nthr){
  int tot=(K/2)*64;
  for(int i=tid;i<tot;i+=nthr){
    int kp=i>>6,c=i&63;
    u64 v=mk2(src[(2*kp)*64+c],src[(2*kp+1)*64+c]);
    dst[(kp<<6)+((c&2)?32:0)+((c>>2)<<1)+(c&1)]=v;
  }
}
__device__ __forceinline__ void ainit(u64* acc,const float* b4,int q){
  float4 b=*(const float4*)&b4[q*4];
#pragma unroll
  for(int r=0;r<4;r++){
    acc[4*r]=mk2(b.x,0.f); acc[4*r+1]=mk2(b.y,0.f);
    acc[4*r+2]=mk2(b.z,0.f); acc[4*r+3]=mk2(b.w,0.f);
  }
}
__device__ __forceinline__ void a0init(u64* acc){
#pragma unroll
  for(int i=0;i<16;i++) acc[i]=0ull;
}
template<int K>
__device__ __forceinline__ void mv8p(const float* vb,int ST,const u64* Wp,int q,u64* acc){
#pragma unroll 8
  for(int kp=0;kp<K/2;kp+=2){
    ulonglong2 a0=*(const ulonglong2*)(vb+2*kp);
    ulonglong2 a1=*(const ulonglong2*)(vb+ST+2*kp);
    ulonglong2 a2=*(const ulonglong2*)(vb+2*ST+2*kp);
    ulonglong2 a3=*(const ulonglong2*)(vb+3*ST+2*kp);
    const u64* wr=Wp+(kp<<6)+2*q;
    ulonglong2 wa0=*(const ulonglong2*)wr;
    ulonglong2 wb0=*(const ulonglong2*)(wr+32);
    ulonglong2 wa1=*(const ulonglong2*)(wr+64);
    ulonglong2 wb1=*(const ulonglong2*)(wr+96);
#define RSTEP(r,A) \
    acc[4*r+0]=ffma2(A.x,wa0.x,acc[4*r+0]); acc[4*r+1]=ffma2(A.x,wa0.y,acc[4*r+1]); \
    acc[4*r+2]=ffma2(A.x,wb0.x,acc[4*r+2]); acc[4*r+3]=ffma2(A.x,wb0.y,acc[4*r+3]); \
    acc[4*r+0]=ffma2(A.y,wa1.x,acc[4*r+0]); acc[4*r+1]=ffma2(A.y,wa1.y,acc[4*r+1]); \
    acc[4*r+2]=ffma2(A.y,wb1.x,acc[4*r+2]); acc[4*r+3]=ffma2(A.y,wb1.y,acc[4*r+3]);
    RSTEP(0,a0) RSTEP(1,a1) RSTEP(2,a2) RSTEP(3,a3)
#undef RSTEP
  }
}

__global__ void k_zero(){
  int i=blockIdx.x*blockDim.x+threadIdx.x;
  if(i<NN) g_cnt[i]=0.f;
  if(i<NN*3) g_xacc[i]=0.f;
}
__global__ void k_count(const int* __restrict__ erow){
  int e=blockIdx.x*blockDim.x+threadIdx.x;
  if(e<EE) atomicAdd(&g_cnt[erow[e]],1.f);
}

// h0=h16@Wi+bi ; A=h0@EA+eb ; B=h0@EB ; init x, invc, agg=0  (validated)
__global__ void __launch_bounds__(256) k_embed(
    const float* __restrict__ h16,const float* __restrict__ xin,
    const float* __restrict__ Wi,const float* __restrict__ bi,
    const float* __restrict__ EA,const float* __restrict__ eb,
    const float* __restrict__ EB){
  extern __shared__ char sr[];
  u64* sWip=(u64*)sr; u64* sEAp=(u64*)(sr+4096); u64* sEBp=(u64*)(sr+20480);
  float* sbi=(float*)(sr+36864); float* seb=(float*)(sr+37120);
  float* vbase=(float*)(sr+37376);
  const int tid=threadIdx.x,wid=tid>>5,lane=tid&31,q=lane&15,g2=lane>>4;
  stageW(sWip,Wi,16,tid,256);
  stageW(sEAp,EA,64,tid,256);
  stageW(sEBp,EB,64,tid,256);
  if(tid<64){sbi[tid]=bi[tid];seb[tid]=eb[tid];}
  float* vb=vbase+wid*(8*84);
  int nbase=blockIdx.x*64+wid*8;
#pragma unroll
  for(int t=0;t<4;t++){
    int e=t*2+g2,n=nbase+e;
    if(q<4){
      float4 v=make_float4(0,0,0,0);
      if(n<NN) v=*(const float4*)&h16[n*16+q*4];
      *(float4*)&vb[e*84+q*4]=v;
    }
    if(n<NN) *(float4*)&g_agg[n*64+q*4]=make_float4(0,0,0,0);
  }
  if(lane<8){int n=nbase+lane; if(n<NN) g_invc[n]=__fdividef(1.f,fmaxf(g_cnt[n],1.f));}
  if(lane<24){int e=lane/3,d=lane-3*(lane/3),n=nbase+e; if(n<NN) g_x[n*3+d]=xin[n*3+d];}
  __syncthreads();
  u64 acc[16];
  ainit(acc,sbi,q);
  mv8p<16>(vb+g2*4*84,84,sWip,q,acc);
  __syncwarp();
#pragma unroll
  for(int r=0;r<4;r++){
    int e=g2*4+r,n=nbase+e;
    float4 h0=make_float4(fin(acc[4*r]),fin(acc[4*r+1]),fin(acc[4*r+2]),fin(acc[4*r+3]));
    *(float4*)&vb[e*84+16+q*4]=h0;
    if(n<NN) *(float4*)&g_h[n*64+q*4]=h0;
  }
  __syncwarp();
  ainit(acc,seb,q);
  mv8p<64>(vb+g2*4*84+16,84,sEAp,q,acc);
#pragma unroll
  for(int r=0;r<4;r++){
    int n=nbase+g2*4+r;
    if(n<NN) *(float4*)&g_A[n*64+q*4]=make_float4(fin(acc[4*r]),fin(acc[4*r+1]),fin(acc[4*r+2]),fin(acc[4*r+3]));
  }
  a0init(acc);
  mv8p<64>(vb+g2*4*84+16,84,sEBp,q,acc);
#pragma unroll
  for(int r=0;r<4;r++){
    int n=nbase+g2*4+r;
    if(n<NN) *(float4*)&g_B[n*64+q*4]=make_float4(fin(acc[4*r]),fin(acc[4*r+1]),fin(acc[4*r+2]),fin(acc[4*r+3]));
  }
}

// ======== edge kernel: 16 edges/warp, 128 edges/block, 3 CTAs/SM (R15-validated epilogues) ========
__global__ void __launch_bounds__(256,3) k_edge(
    const int* __restrict__ erow,const int* __restrict__ ecol,
    const float* __restrict__ w1c,const float* __restrict__ W2,
    const float* __restrict__ b2,const float* __restrict__ CW1,
    const float* __restrict__ cb1,const float* __restrict__ cw2){
  extern __shared__ char sr[];
  float* sW2=(float*)sr; float* sC1=(float*)(sr+16384);
  float* sw1c=(float*)(sr+32768); float* sb2=(float*)(sr+33024);
  float* scb1=(float*)(sr+33280); float* scw2=(float*)(sr+33536);
  float* wsmb=(float*)(sr+33792);
  const int tid=threadIdx.x,wid=tid>>5,lane=tid&31,q=lane&15,g2=lane>>4;
  for(int i=tid;i<1024;i+=256){((float4*)sW2)[i]=((const float4*)W2)[i];((float4*)sC1)[i]=((const float4*)CW1)[i];}
  if(tid<64){sw1c[tid]=w1c[tid];sb2[tid]=b2[tid];scb1[tid]=cb1[tid];scw2[tid]=cw2[tid];}
  float* wsm=wsmb+wid*1216;
  float* m1b=wsm;                 // 1088 floats, reused as mb after matvec1
  float* dfb=wsm+1088; float* rdb=wsm+1136; float* icb=wsm+1152;
  int* rwb=(int*)(wsm+1168); int* clb=(int*)(wsm+1184);
  int ebase=blockIdx.x*128+wid*16;
  if(lane<16){
    int e=ebase+lane,r=erow[e],c=ecol[e];
    rwb[lane]=r; clb[lane]=c;
    float dx=g_x[r*3]-g_x[c*3],dy=g_x[r*3+1]-g_x[c*3+1],dz=g_x[r*3+2]-g_x[c*3+2];
    dfb[lane*3]=dx; dfb[lane*3+1]=dy; dfb[lane*3+2]=dz;
    rdb[lane]=dx*dx+dy*dy+dz*dz; icb[lane]=g_invc[r];
  }
  __syncthreads();
  { // m1 = silu(A[r]+B[c]+rad*w1c), 16 edges
    float4 wc=*(const float4*)&sw1c[q*4];
#pragma unroll
    for(int t=0;t<8;t++){
      int e=t*2+g2;
      float4 av=*(const float4*)&g_A[rwb[e]*64+q*4];
      float4 bv=*(const float4*)&g_B[clb[e]*64+q*4];
      float rad=rdb[e];
      *(float4*)&m1b[e*68+q*4]=make_float4(
        silu(av.x+bv.x+rad*wc.x), silu(av.y+bv.y+rad*wc.y),
        silu(av.z+bv.z+rad*wc.z), silu(av.w+bv.w+rad*wc.w));
    }
  }
  __syncwarp();
  u64 accA[8],accB[8];
  acc_init8(accA,sb2,q); acc_init8(accB,sb2,q);
  mv8d<64>(m1b+g2*68,sW2,q,accA,accB);
  __syncwarp();          // all lanes done reading m1b before overwrite
#pragma unroll
  for(int r=0;r<8;r++){
    int e=2*r+g2;
    const u64* ac=(r<4)?(accA+2*(r&3)):(accB+2*(r&3));
    float2 lo=unpk(ac[0]),hi=unpk(ac[1]);
    float m0=silu(lo.x),m1=silu(lo.y),m2=silu(hi.x),m3=silu(hi.y);
    *(float4*)&m1b[e*68+q*4]=make_float4(m0,m1,m2,m3);
    float* ap=&g_agg[rwb[e]*64+q*4];
    asm volatile("red.global.add.v4.f32 [%0],{%1,%2,%3,%4};"
                 ::"l"(ap),"f"(m0),"f"(m1),"f"(m2),"f"(m3):"memory");
  }
  __syncwarp();
  acc_init8(accA,scb1,q); acc_init8(accB,scb1,q);
  mv8d<64>(m1b+g2*68,sC1,q,accA,accB);
  float4 c4=*(const float4*)&scw2[q*4];
  float s[8];
#pragma unroll
  for(int r=0;r<8;r++){
    const u64* ac=(r<4)?(accA+2*(r&3)):(accB+2*(r&3));
    float2 lo=unpk(ac[0]),hi=unpk(ac[1]);
    s[r]=silu(lo.x)*c4.x+silu(lo.y)*c4.y+silu(hi.x)*c4.z+silu(hi.y)*c4.w;
  }
#pragma unroll
  for(int off=1;off<16;off<<=1){
#pragma unroll
    for(int r=0;r<8;r++) s[r]+=__shfl_xor_sync(0xffffffffu,s[r],off);
  }
  if(q<12){
    int j=q/3,d=q-3*j;
    int e0=2*j+g2, e1=2*(j+4)+g2;
    atomicAdd(&g_xacc[rwb[e0]*3+d], dfb[e0*3+d]*s[j]*icb[e0]);
    atomicAdd(&g_xacc[rwb[e1]*3+d], dfb[e1*3+d]*s[j+4]*icb[e1]);
  }
}

// ======== node kernel: single 32KB weight buffer, re-staged per phase, 3 CTAs/SM (validated R15) ========
__global__ void __launch_bounds__(256,3) k_node(
    const float* __restrict__ NW1,const float* __restrict__ nb1,
    const float* __restrict__ NW2,const float* __restrict__ nb2,
    const float* __restrict__ WA,const float* __restrict__ ba,
    const float* __restrict__ WB,int last,float* __restrict__ outp){
  extern __shared__ char sr[];
  u64* W0=(u64*)sr;
  float* snb1=(float*)(sr+32768); float* snb2=(float*)(sr+33024);
  float* sba=(float*)(sr+33280);
  float* vbase=(float*)(sr+33536);
  const int tid=threadIdx.x,wid=tid>>5,lane=tid&31,q=lane&15,g2=lane>>4;
  stageW(W0,NW1,128,tid,256);
  if(tid<64){snb1[tid]=nb1[tid];snb2[tid]=nb2[tid];sba[tid]=ba[tid];}
  float* vb=vbase+wid*1056;
  int nbase=blockIdx.x*64+wid*8;
#pragma unroll
  for(int t=0;t<4;t++){
    int e=t*2+g2,n=nbase+e;
    float4 h4=make_float4(0,0,0,0),a4=make_float4(0,0,0,0);
    if(n<NN){
      h4=*(const float4*)&g_h[n*64+q*4];
      a4=*(const float4*)&g_agg[n*64+q*4];
      *(float4*)&g_agg[n*64+q*4]=make_float4(0,0,0,0);
    }
    *(float4*)&vb[e*132+q*4]=h4;
    *(float4*)&vb[e*132+64+q*4]=a4;
  }
  if(lane<24){
    int e=lane/3,d=lane-3*(lane/3),n=nbase+e;
    if(n<NN){
      float nx=g_x[n*3+d]+g_xacc[n*3+d];
      g_x[n*3+d]=nx; g_xacc[n*3+d]=0.f;
      if(last) outp[NN*64+n*3+d]=nx;
    }
  }
  __syncthreads();
  u64 acc[16];
  ainit(acc,snb1,q);
  mv8p<128>(vb+g2*4*132,132,W0,q,acc);
  __syncwarp();
#pragma unroll
  for(int r=0;r<4;r++){
    int e=g2*4+r;
    *(float4*)&vb[e*132+64+q*4]=make_float4(
      silu(fin(acc[4*r])),silu(fin(acc[4*r+1])),silu(fin(acc[4*r+2])),silu(fin(acc[4*r+3])));
  }
  __syncthreads();
  stageW(W0,NW2,64,tid,256);      // NW1 dead
  __syncthreads();
  ainit(acc,snb2,q);
  mv8p<64>(vb+g2*4*132+64,132,W0,q,acc);
  __syncwarp();
#pragma unroll
  for(int r=0;r<4;r++){
    int e=g2*4+r,n=nbase+e;
    float4 ho=*(const float4*)&vb[e*132+q*4];
    float4 hn=make_float4(ho.x+fin(acc[4*r]),ho.y+fin(acc[4*r+1]),
                          ho.z+fin(acc[4*r+2]),ho.w+fin(acc[4*r+3]));
    *(float4*)&vb[e*132+q*4]=hn;
    if(n<NN) *(float4*)&g_h[n*64+q*4]=hn;
  }
  __syncthreads();
  stageW(W0,WA,64,tid,256);       // NW2 dead
  if(!last) stageW(W0+2048,WB,64,tid,256);
  __syncthreads();
  ainit(acc,sba,q);
  mv8p<64>(vb+g2*4*132,132,W0,q,acc);
  if(last){
#pragma unroll
    for(int r=0;r<4;r++){
      int n=nbase+g2*4+r;
      if(n<NN) *(float4*)&outp[n*64+q*4]=make_float4(fin(acc[4*r]),fin(acc[4*r+1]),fin(acc[4*r+2]),fin(acc[4*r+3]));
    }
  } else {
#pragma unroll
    for(int r=0;r<4;r++){
      int n=nbase+g2*4+r;
      if(n<NN) *(float4*)&g_A[n*64+q*4]=make_float4(fin(acc[4*r]),fin(acc[4*r+1]),fin(acc[4*r+2]),fin(acc[4*r+3]));
    }
    a0init(acc);
    mv8p<64>(vb+g2*4*132,132,W0+2048,q,acc);
#pragma unroll
    for(int r=0;r<4;r++){
      int n=nbase+g2*4+r;
      if(n<NN) *(float4*)&g_B[n*64+q*4]=make_float4(fin(acc[4*r]),fin(acc[4*r+1]),fin(acc[4*r+2]),fin(acc[4*r+3]));
    }
  }
}

extern "C" void kernel_launch(void* const* d_in,const int* in_sizes,int n_in,
                              void* d_out,int out_size){
  const float* h16=(const float*)d_in[0];
  const float* xin=(const float*)d_in[1];
  const int*   ei =(const int*  )d_in[2];
  const float* Wi =(const float*)d_in[3];
  const float* bi =(const float*)d_in[4];
  const float* ew1=(const float*)d_in[5];
  const float* eb1=(const float*)d_in[6];
  const float* ew2=(const float*)d_in[7];
  const float* eb2=(const float*)d_in[8];
  const float* cw1=(const float*)d_in[9];
  const float* cb1=(const float*)d_in[10];
  const float* cw2=(const float*)d_in[11];
  const float* nw1=(const float*)d_in[12];
  const float* nb1=(const float*)d_in[13];
  const float* nw2=(const float*)d_in[14];
  const float* nb2=(const float*)d_in[15];
  const float* Wo =(const float*)d_in[16];
  const float* bo =(const float*)d_in[17];
  float* outp=(float*)d_out;
  const int* erow=ei; const int* ecol=ei+EE;

  const int SME=58880, SMEDGE=(8448+8*1216)*4, SMN=67328;
  cudaFuncSetAttribute(k_embed,cudaFuncAttributeMaxDynamicSharedMemorySize,SME);
  cudaFuncSetAttribute(k_edge, cudaFuncAttributeMaxDynamicSharedMemorySize,SMEDGE);
  cudaFuncSetAttribute(k_node, cudaFuncAttributeMaxDynamicSharedMemorySize,SMN);

  const int NB=(NN+63)/64;
  k_zero<<<(NN*3+255)/256,256>>>();
  k_count<<<(EE+255)/256,256>>>(erow);
  k_embed<<<NB,256,SME>>>(h16,xin,Wi,bi,ew1,eb1,ew1+64*64);
  for(int l=0;l<4;l++){
    k_edge<<<EE/128,256,SMEDGE>>>(erow,ecol,ew1+l*129*64+128*64,ew2+l*4096,eb2+l*64,
                                  cw1+l*4096,cb1+l*64,cw2+l*64);
    int last=(l==3);
    const float* WA = last ? Wo : ew1+(l+1)*129*64;
    const float* ba = last ? bo : eb1+(l+1)*64;
    const float* WB = last ? Wo : WA+64*64;
    k_node<<<NB,256,SMN>>>(nw1+l*128*64,nb1+l*64,nw2+l*4096,nb2+l*64,WA,ba,WB,last,outp);
  }
}